// round 16
// baseline (speedup 1.0000x reference)
#include <cuda_runtime.h>
#include <math.h>

// feat: [B=4, C=256, H=50, W=50] f32;  rois: [R,5] f32;  out: [R,256,7,7] f32
#define BB 4
#define CC 256
#define HW 2500
#define HH 50
#define WW 50
#define PP 7
#define NBIN 49
#define SPATIAL_SCALE 0.0625f
#define MAX_R 512
#define GW 64                       // channels per gather block

// Channel-last features: featT[b][cell][c].
__device__ __align__(16) float g_featT[BB * HW * CC];
// Per-(roi,bin): x = (b*HW + hs*50 + ws)*CC  (featT float offset), y = 4x4 mask.
__device__ int2 g_tab[MAX_R * NBIN];

// ---------- transpose [b][c][s] -> [b][s][c]: register 4x4, all-vector ----------
__global__ void __launch_bounds__(256)
transpose_kernel(const float* __restrict__ feat) {
    __shared__ float4 tile4[64][17];            // [c][s-quad], +1 quad pad
    const int s0q = blockIdx.x * 16;            // s-quad origin (625 quads total)
    const int c0  = blockIdx.y * 64;
    const int b   = blockIdx.z;
    const int t   = threadIdx.x;

    {   // read: thread (cr, sq0) loads quads sq0+4k of channel row c0+cr
        const int cr = t >> 2, sq0 = t & 3;
        const float4* src = (const float4*)(feat + ((size_t)(b * CC + c0 + cr)) * HW) + s0q;
        #pragma unroll
        for (int k = 0; k < 4; ++k) {
            int q = sq0 + 4 * k;
            if (s0q + q < HW / 4) tile4[cr][q] = __ldg(src + q);
        }
    }
    __syncthreads();
    {   // write: thread (sp, cp) transposes a 4x4 patch in registers
        const int sp = t >> 4, cp = t & 15;
        if (s0q + sp < HW / 4) {
            float4 a = tile4[cp * 4 + 0][sp];
            float4 bv = tile4[cp * 4 + 1][sp];
            float4 cv = tile4[cp * 4 + 2][sp];
            float4 dv = tile4[cp * 4 + 3][sp];
            float4* dst = (float4*)(g_featT
                + ((size_t)(b * HW) + (size_t)(s0q + sp) * 4) * CC + c0) + cp;
            dst[0 * (CC / 4)] = make_float4(a.x, bv.x, cv.x, dv.x);
            dst[1 * (CC / 4)] = make_float4(a.y, bv.y, cv.y, dv.y);
            dst[2 * (CC / 4)] = make_float4(a.z, bv.z, cv.z, dv.z);
            dst[3 * (CC / 4)] = make_float4(a.w, bv.w, cv.w, dv.w);
        }
    }
}

// ---------- setup: per-(roi,bin) address + mask ----------
__global__ void roi_setup_kernel(const float* __restrict__ rois) {
    const int r = blockIdx.x;
    const int p = threadIdx.x;                  // 0..48
    const float* rp = rois + (size_t)r * 5;

    // jnp.round == round-half-to-even == rintf (RN); *0.0625 exact.
    float x1 = rintf(rp[1] * SPATIAL_SCALE);
    float y1 = rintf(rp[2] * SPATIAL_SCALE);
    float x2 = rintf(rp[3] * SPATIAL_SCALE);
    float y2 = rintf(rp[4] * SPATIAL_SCALE);
    // XLA folds x/7 into x * RN(1/7); replicate exactly.
    const float INV7 = 1.0f / 7.0f;
    float bw = __fmul_rn(fmaxf(x2 - x1 + 1.0f, 1.0f), INV7);
    float bh = __fmul_rn(fmaxf(y2 - y1 + 1.0f, 1.0f), INV7);
    float fpw = (float)(p % PP);
    float fph = (float)(p / PP);
    int ws = (int)fminf(fmaxf(floorf(__fmul_rn(bw, fpw))        + x1, 0.0f), (float)WW);
    int we = (int)fminf(fmaxf(ceilf (__fmul_rn(bw, fpw + 1.0f)) + x1, 0.0f), (float)WW);
    int hs = (int)fminf(fmaxf(floorf(__fmul_rn(bh, fph))        + y1, 0.0f), (float)HH);
    int he = (int)fminf(fmaxf(ceilf (__fmul_rn(bh, fph + 1.0f)) + y1, 0.0f), (float)HH);
    int nw = we - ws;                           // 0..4 (window provably <= 4x4)
    int nh = he - hs;
    unsigned rowpat = (nw > 0) ? ((1u << nw) - 1u) : 0u;
    unsigned rows   = (nh > 0) ? (0x1111u & ((1u << (4 * nh)) - 1u)) : 0u;
    int b = (int)rp[0];
    g_tab[r * NBIN + p] = make_int2((b * HW + hs * WW + ws) * CC,
                                    (int)(rowpat * rows));
}

// ---------- gather: block = (roi, 64ch); warp = 7 bins; lane = 2 channels ----------
__global__ void __launch_bounds__(224)
roipool_kernel(float* __restrict__ out) {
    __shared__ float s_out[NBIN][68];           // stride 68 (272B, 8B-aligned cols)

    const int r  = blockIdx.x;
    const int c0 = blockIdx.y * GW;
    const int t  = threadIdx.x;
    const int lane = t & 31;
    const int w    = t >> 5;                    // 0..6

    const int2* tab = g_tab + r * NBIN;

    #pragma unroll 1
    for (int q = 0; q < PP; ++q) {
        const int p = q * PP + w;               // covers 0..48 exactly
        int2 tb = __ldg(&tab[p]);
        const unsigned mask = (unsigned)tb.y;   // warp-uniform
        const float2* base = (const float2*)(g_featT + tb.x + c0) + lane;

        float m0 = -INFINITY, m1 = -INFINITY;
        #pragma unroll
        for (int i = 0; i < 4; ++i) {
            #pragma unroll
            for (int j = 0; j < 4; ++j) {
                if (mask & (1u << (i * 4 + j))) {
                    float2 v = __ldg(base + (i * WW + j) * (CC / 2));
                    m0 = fmaxf(m0, v.x);
                    m1 = fmaxf(m1, v.y);
                }
            }
        }
        float2 o;
        o.x = (m0 == -INFINITY) ? 0.0f : m0;
        o.y = (m1 == -INFINITY) ? 0.0f : m1;
        *(float2*)&s_out[p][2 * lane] = o;
    }
    __syncthreads();

    // Writeback: one contiguous 3136-float range, perfectly coalesced.
    float* ob = out + ((size_t)r * CC + c0) * NBIN;
    #pragma unroll
    for (int k = 0; k < 14; ++k) {
        int o = t + 224 * k;                    // 0..3135
        int c = o / NBIN;
        int p = o - c * NBIN;
        ob[o] = s_out[p][c];
    }
}

extern "C" void kernel_launch(void* const* d_in, const int* in_sizes, int n_in,
                              void* d_out, int out_size) {
    const float* feat = (const float*)d_in[0];
    const float* rois = (const float*)d_in[1];
    float* out = (float*)d_out;

    int R = in_sizes[1] / 5;                     // 128

    dim3 tgrid(40, CC / 64, BB);                 // 40 x 4 x 4 = 640
    transpose_kernel<<<tgrid, 256>>>(feat);

    roi_setup_kernel<<<R, NBIN>>>(rois);

    dim3 ggrid(R, CC / GW);                      // 128 x 4 = 512
    roipool_kernel<<<ggrid, 224>>>(out);
}

// round 17
// speedup vs baseline: 1.2691x; 1.2691x over previous
#include <cuda_runtime.h>
#include <math.h>

// feat: [B=4, C=256, H=50, W=50] f32;  rois: [R,5] f32;  out: [R,256,7,7] f32
#define BB 4
#define CC 256
#define HW 2500
#define HH 50
#define WW 50
#define PP 7
#define NBIN 49
#define SPATIAL_SCALE 0.0625f
#define MAX_R 512

// Channel-last features: featT[b][cell][c].
__device__ __align__(16) float g_featT[BB * HW * CC];
// Per-(roi,bin): x = (b*HW + hs*50 + ws)*CC (featT float offset), y = 4x4 mask.
__device__ int2 g_tab[MAX_R * NBIN];

// ---------- transpose [b][c][s] -> [b][s][c]: many small blocks ----------
// Tile: 64 channels x 16 cells. 2512 blocks -> latency fully hidden.
#define TSTRIDE 21
__global__ void __launch_bounds__(256)
transpose_kernel(const float* __restrict__ feat) {
    __shared__ float tile[64][TSTRIDE];         // [c_local][cell_local]
    const int s0q = blockIdx.x * 4;             // quad origin (625 quads total)
    const int c0  = blockIdx.y * 64;
    const int b   = blockIdx.z;
    const int t   = threadIdx.x;

    {   // read: thread (cl, sq) loads one float4 (4 cells) of channel c0+cl
        const int cl = t >> 2, sq = t & 3;
        const int q = s0q + sq;
        if (q < HW / 4) {
            float4 v = __ldg((const float4*)feat + (size_t)(b * CC + c0 + cl) * (HW / 4) + q);
            tile[cl][sq * 4 + 0] = v.x;
            tile[cl][sq * 4 + 1] = v.y;
            tile[cl][sq * 4 + 2] = v.z;
            tile[cl][sq * 4 + 3] = v.w;
        }
    }
    __syncthreads();
    {   // write: thread (sl, cq) stores one float4 over channels for one cell
        const int sl = t >> 4, cq = t & 15;
        const int cell = s0q * 4 + sl;
        if (cell < HW) {
            float4 v;
            v.x = tile[cq * 4 + 0][sl];
            v.y = tile[cq * 4 + 1][sl];
            v.z = tile[cq * 4 + 2][sl];
            v.w = tile[cq * 4 + 3][sl];
            *((float4*)(g_featT + ((size_t)(b * HW) + cell) * CC + c0) + cq) = v;
        }
    }
}

// ---------- setup: per-(roi,bin) address + mask ----------
__global__ void roi_setup_kernel(const float* __restrict__ rois) {
    const int r = blockIdx.x;
    const int p = threadIdx.x;                  // 0..48
    const float* rp = rois + (size_t)r * 5;

    // jnp.round == round-half-to-even == rintf (RN); *0.0625 exact.
    float x1 = rintf(rp[1] * SPATIAL_SCALE);
    float y1 = rintf(rp[2] * SPATIAL_SCALE);
    float x2 = rintf(rp[3] * SPATIAL_SCALE);
    float y2 = rintf(rp[4] * SPATIAL_SCALE);
    // XLA folds x/7 into x * RN(1/7); replicate exactly.
    const float INV7 = 1.0f / 7.0f;
    float bw = __fmul_rn(fmaxf(x2 - x1 + 1.0f, 1.0f), INV7);
    float bh = __fmul_rn(fmaxf(y2 - y1 + 1.0f, 1.0f), INV7);
    float fpw = (float)(p % PP);
    float fph = (float)(p / PP);
    int ws = (int)fminf(fmaxf(floorf(__fmul_rn(bw, fpw))        + x1, 0.0f), (float)WW);
    int we = (int)fminf(fmaxf(ceilf (__fmul_rn(bw, fpw + 1.0f)) + x1, 0.0f), (float)WW);
    int hs = (int)fminf(fmaxf(floorf(__fmul_rn(bh, fph))        + y1, 0.0f), (float)HH);
    int he = (int)fminf(fmaxf(ceilf (__fmul_rn(bh, fph + 1.0f)) + y1, 0.0f), (float)HH);
    int nw = we - ws;                           // 0..4 (window provably <= 4x4)
    int nh = he - hs;
    unsigned rowpat = (nw > 0) ? ((1u << nw) - 1u) : 0u;
    unsigned rows   = (nh > 0) ? (0x1111u & ((1u << (4 * nh)) - 1u)) : 0u;
    int b = (int)rp[0];
    g_tab[r * NBIN + p] = make_int2((b * HW + hs * WW + ws) * CC,
                                    (int)(rowpat * rows));
}

// ---------- gather: warp = one bin, lane = 4 channels (R15 structure) ----------
// Block = (pg, cg, r): 7 warps = bins p = pg*7+w; 128 channels c0 = cg*128.
__global__ void __launch_bounds__(224)
roipool_kernel(float* __restrict__ out) {
    __shared__ __align__(16) float s_out[PP][132];

    const int pg = blockIdx.x;           // 0..6
    const int c0 = blockIdx.y << 7;      // 0 or 128
    const int r  = blockIdx.z;
    const int t    = threadIdx.x;
    const int lane = t & 31;
    const int w    = t >> 5;             // 0..6
    const int p    = pg * PP + w;        // 0..48 exactly

    const int2 tb = __ldg(&g_tab[r * NBIN + p]);
    const unsigned mask = (unsigned)tb.y;        // warp-uniform
    const float4* base = (const float4*)(g_featT + tb.x + c0) + lane;

    // Each taken slot = one coalesced 512B LDG.128 wavefront group.
    float m0 = -INFINITY, m1 = -INFINITY, m2 = -INFINITY, m3 = -INFINITY;
    #pragma unroll
    for (int i = 0; i < 4; ++i) {
        #pragma unroll
        for (int j = 0; j < 4; ++j) {
            if (mask & (1u << (i * 4 + j))) {
                float4 v = __ldg(base + (i * WW + j) * (CC / 4));
                m0 = fmaxf(m0, v.x);
                m1 = fmaxf(m1, v.y);
                m2 = fmaxf(m2, v.z);
                m3 = fmaxf(m3, v.w);
            }
        }
    }
    float4 o;
    o.x = (m0 == -INFINITY) ? 0.0f : m0;
    o.y = (m1 == -INFINITY) ? 0.0f : m1;
    o.z = (m2 == -INFINITY) ? 0.0f : m2;
    o.w = (m3 == -INFINITY) ? 0.0f : m3;
    ((float4*)&s_out[w][0])[lane] = o;
    __syncthreads();

    // Writeback: 896 outputs = 128 c x 7 ww; out[(r*256+c0+c)*49 + pg*7 + ww].
    #pragma unroll
    for (int k = 0; k < 4; ++k) {
        int oidx = t + 224 * k;          // 0..895
        int c  = oidx / PP;
        int ww = oidx - c * PP;
        out[((size_t)(r * CC + c0 + c)) * NBIN + pg * PP + ww] = s_out[ww][c];
    }
}

extern "C" void kernel_launch(void* const* d_in, const int* in_sizes, int n_in,
                              void* d_out, int out_size) {
    const float* feat = (const float*)d_in[0];
    const float* rois = (const float*)d_in[1];
    float* out = (float*)d_out;

    int R = in_sizes[1] / 5;                     // 128

    dim3 tgrid(157, CC / 64, BB);                // 157 x 4 x 4 = 2512
    transpose_kernel<<<tgrid, 256>>>(feat);

    roi_setup_kernel<<<R, NBIN>>>(rois);

    dim3 ggrid(PP, CC / 128, R);                 // 7 x 2 x 128 = 1792
    roipool_kernel<<<ggrid, 224>>>(out);
}